// round 13
// baseline (speedup 1.0000x reference)
#include <cuda_runtime.h>
#include <cuda_bf16.h>
#include <math.h>
#include <stdint.h>

// ---------------------------------------------------------------------------
// Problem constants
// ---------------------------------------------------------------------------
#define BATCH   2
#define SEQ     2048
#define DMODEL  1024
#define NHEADS  16
#define DK      64
#define MTOT    (BATCH * SEQ)        // 4096
#define SCALE   0.125f               // 1/sqrt(64)
#define WSZ     (DMODEL * DMODEL)

// ---------------------------------------------------------------------------
// Scratch (__device__ globals; allocation-free rule)
// ---------------------------------------------------------------------------
__device__ __nv_bfloat16 g_ahi[MTOT * DMODEL];
__device__ __nv_bfloat16 g_alo[MTOT * DMODEL];
__device__ __nv_bfloat16 g_whi[4 * WSZ];
__device__ __nv_bfloat16 g_wlo[4 * WSZ];
__device__ __nv_bfloat16 g_qhi[MTOT * DMODEL];
__device__ __nv_bfloat16 g_qlo[MTOT * DMODEL];
__device__ __nv_bfloat16 g_khi[MTOT * DMODEL];
__device__ __nv_bfloat16 g_klo[MTOT * DMODEL];
__device__ __nv_bfloat16 g_vthi[MTOT * DMODEL];
__device__ __nv_bfloat16 g_vtlo[MTOT * DMODEL];
__device__ float2 g_cs[SEQ * (DK / 2)];

// ---------------------------------------------------------------------------
// PTX helpers
// ---------------------------------------------------------------------------
__device__ __forceinline__ uint32_t smem_to_u32(const void* p) {
    uint32_t a;
    asm("{ .reg .u64 t; cvta.to.shared.u64 t, %1; cvt.u32.u64 %0, t; }"
        : "=r"(a) : "l"(p));
    return a;
}

__device__ __forceinline__ void cp_async16(uint32_t dst, const void* src) {
    asm volatile("cp.async.cg.shared.global [%0], [%1], 16;" :: "r"(dst), "l"(src));
}

__device__ __forceinline__ void ldsm4(uint32_t* r, uint32_t addr) {
    asm volatile("ldmatrix.sync.aligned.m8n8.x4.shared.b16 {%0,%1,%2,%3}, [%4];"
                 : "=r"(r[0]), "=r"(r[1]), "=r"(r[2]), "=r"(r[3]) : "r"(addr));
}

__device__ __forceinline__ void mma_bf16(float* d, const uint32_t* a, const uint32_t* b) {
    asm volatile(
        "mma.sync.aligned.m16n8k16.row.col.f32.bf16.bf16.f32 "
        "{%0,%1,%2,%3}, {%4,%5,%6,%7}, {%8,%9}, {%0,%1,%2,%3};"
        : "+f"(d[0]), "+f"(d[1]), "+f"(d[2]), "+f"(d[3])
        : "r"(a[0]), "r"(a[1]), "r"(a[2]), "r"(a[3]), "r"(b[0]), "r"(b[1]));
}

__device__ __forceinline__ uint32_t pack2bf(float a, float b) {
    __nv_bfloat162 t = __floats2bfloat162_rn(a, b);
    return *reinterpret_cast<uint32_t*>(&t);
}
__device__ __forceinline__ float bf_round(float x) {
    return __bfloat162float(__float2bfloat16(x));
}
__device__ __forceinline__ void store_split2(
    __nv_bfloat16* hi, __nv_bfloat16* lo, size_t off, float a, float b)
{
    __nv_bfloat16 ha = __float2bfloat16(a), hb = __float2bfloat16(b);
    *(__nv_bfloat162*)(hi + off) = __nv_bfloat162(ha, hb);
    *(__nv_bfloat162*)(lo + off) = __nv_bfloat162(
        __float2bfloat16(a - __bfloat162float(ha)),
        __float2bfloat16(b - __bfloat162float(hb)));
}

// ---------------------------------------------------------------------------
// GEMM mainloop (NT, bf16x3, 128x128 tile, BK=32, 3-stage cp.async,
// SW64-swizzled unpadded 64B-row smem, single barrier per chunk).
// ---------------------------------------------------------------------------
#define MAT_B   8192u                // 128 rows * 64 B
#define STAGE_B 32768u               // Ahi|Alo|Bhi|Blo
#define GEMM_SMEM (3 * STAGE_B)      // 98304 B

__device__ __forceinline__ uint32_t sw64(int row, int seg) {
    return (uint32_t)(row * 64 + ((seg ^ ((row >> 1) & 3)) << 4));
}

__device__ __forceinline__ void gemm_issue(
    uint32_t dstHi, uint32_t dstLo,
    const __nv_bfloat16* srcHi, const __nv_bfloat16* srcLo, int t, int k0)
{
#pragma unroll
    for (int i = 0; i < 4; i++) {
        int chunk = t + (i << 7);
        int row = chunk >> 2, seg = chunk & 3;
        uint32_t so = sw64(row, seg);
        const size_t go = (size_t)row * DMODEL + k0 + seg * 8;
        cp_async16(dstHi + so, srcHi + go);
        cp_async16(dstLo + so, srcLo + go);
    }
    asm volatile("cp.async.commit_group;" ::: "memory");
}

__device__ __forceinline__ void gemm_mainloop(
    uint32_t sb, int tid, int wid, int lane,
    const __nv_bfloat16* __restrict__ Ahi, const __nv_bfloat16* __restrict__ Alo,
    const __nv_bfloat16* __restrict__ Bhi, const __nv_bfloat16* __restrict__ Blo,
    int bm, int bn, float acc[4][4][4])
{
    const bool isA = tid < 128;
    const int t = isA ? tid : tid - 128;
    const __nv_bfloat16* srcHi = isA ? (Ahi + (size_t)bm * DMODEL)
                                     : (Bhi + (size_t)bn * DMODEL);
    const __nv_bfloat16* srcLo = isA ? (Alo + (size_t)bm * DMODEL)
                                     : (Blo + (size_t)bn * DMODEL);
    const uint32_t matHiOff = isA ? 0u : 2u * MAT_B;
    const uint32_t matLoOff = matHiOff + MAT_B;

#pragma unroll
    for (int i = 0; i < 4; i++)
#pragma unroll
        for (int j = 0; j < 4; j++)
#pragma unroll
            for (int e = 0; e < 4; e++) acc[i][j][e] = 0.f;

    const int mwarp = wid & 1, nwarp = wid >> 1;

    const int arowb = mwarp * 64 + (lane & 7) + ((lane >> 3) & 1) * 8;
    const int asegb = (lane >> 4) & 1;
    const int browb = nwarp * 32 + ((lane >> 4) & 1) * 8 + (lane & 7);
    const int bsegb = (lane >> 3) & 1;

    gemm_issue(sb + matHiOff, sb + matLoOff, srcHi, srcLo, t, 0);
    gemm_issue(sb + STAGE_B + matHiOff, sb + STAGE_B + matLoOff, srcHi, srcLo, t, 32);

    for (int c = 0; c < 32; c++) {
        if (c < 31) asm volatile("cp.async.wait_group 1;" ::: "memory");
        else        asm volatile("cp.async.wait_group 0;" ::: "memory");
        __syncthreads();

        if (c + 2 < 32) {
            const uint32_t base = sb + (uint32_t)((c + 2) % 3) * STAGE_B;
            gemm_issue(base + matHiOff, base + matLoOff, srcHi, srcLo, t, (c + 2) * 32);
        }

        const uint32_t stg = sb + (uint32_t)(c % 3) * STAGE_B;
        const uint32_t aHi = stg, aLo = stg + MAT_B;
        const uint32_t bHi = stg + 2u * MAT_B, bLo = stg + 3u * MAT_B;

#pragma unroll
        for (int ks = 0; ks < 2; ks++) {
            const int segA = ks * 2 + asegb;
            const int segB = ks * 2 + bsegb;

            uint32_t af[4][4], bh[2][4], bl[2][4];
#pragma unroll
            for (int mf = 0; mf < 4; mf++) {
                int row = arowb + mf * 16;
                ldsm4(af[mf], aHi + sw64(row, segA));
            }
#pragma unroll
            for (int p = 0; p < 2; p++) {
                int row = browb + p * 16;
                uint32_t off = sw64(row, segB);
                ldsm4(bh[p], bHi + off);
                ldsm4(bl[p], bLo + off);
            }
#pragma unroll
            for (int mf = 0; mf < 4; mf++)
#pragma unroll
                for (int p = 0; p < 2; p++) {
                    mma_bf16(acc[mf][2 * p],     af[mf], &bh[p][0]);
                    mma_bf16(acc[mf][2 * p + 1], af[mf], &bh[p][2]);
                }
#pragma unroll
            for (int mf = 0; mf < 4; mf++)
#pragma unroll
                for (int p = 0; p < 2; p++) {
                    mma_bf16(acc[mf][2 * p],     af[mf], &bl[p][0]);
                    mma_bf16(acc[mf][2 * p + 1], af[mf], &bl[p][2]);
                }
            uint32_t alf[4][4];
#pragma unroll
            for (int mf = 0; mf < 4; mf++) {
                int row = arowb + mf * 16;
                ldsm4(alf[mf], aLo + sw64(row, segA));
            }
#pragma unroll
            for (int mf = 0; mf < 4; mf++)
#pragma unroll
                for (int p = 0; p < 2; p++) {
                    mma_bf16(acc[mf][2 * p],     alf[mf], &bh[p][0]);
                    mma_bf16(acc[mf][2 * p + 1], alf[mf], &bh[p][2]);
                }
        }
    }
}

// ---------------------------------------------------------------------------
// QKV GEMM (2 CTAs/SM): z=0 Q (rope+scale+split), z=1 K (rope+split),
// z=2 V (transpose + split fused via smem staging -> vthi/vtlo directly).
// ---------------------------------------------------------------------------
__global__ __launch_bounds__(256, 2) void gemm_qkv(
    const __nv_bfloat16* __restrict__ Ahi, const __nv_bfloat16* __restrict__ Alo,
    const __nv_bfloat16* __restrict__ Whi, const __nv_bfloat16* __restrict__ Wlo,
    __nv_bfloat16* __restrict__ qhi, __nv_bfloat16* __restrict__ qlo,
    __nv_bfloat16* __restrict__ khi, __nv_bfloat16* __restrict__ klo,
    __nv_bfloat16* __restrict__ vthi, __nv_bfloat16* __restrict__ vtlo,
    const float2* __restrict__ tab)
{
    extern __shared__ char smc[];
    const uint32_t sb = smem_to_u32(smc);
    const int tid = threadIdx.x, wid = tid >> 5, lane = tid & 31;
    const int bm = blockIdx.y * 128, bn = blockIdx.x * 128;
    const int z = blockIdx.z;

    float acc[4][4][4];
    gemm_mainloop(sb, tid, wid, lane, Ahi, Alo,
                  Whi + (size_t)z * WSZ, Wlo + (size_t)z * WSZ, bm, bn, acc);

    const int mwarp = wid & 1, nwarp = wid >> 1;
    const int rbase = bm + mwarp * 64 + (lane >> 2);
    const int cbase = bn + nwarp * 32 + (lane & 3) * 2;

    if (z == 2) {
        float* tile = (float*)smc;               // 128 x 130 fp32
        __syncthreads();
#pragma unroll
        for (int mf = 0; mf < 4; mf++)
#pragma unroll
            for (int nf = 0; nf < 4; nf++)
#pragma unroll
                for (int g = 0; g < 2; g++) {
                    int rl = mwarp * 64 + (lane >> 2) + mf * 16 + g * 8;
                    int cl = nwarp * 32 + (lane & 3) * 2 + nf * 8;
                    tile[rl * 130 + cl]     = acc[mf][nf][2 * g];
                    tile[rl * 130 + cl + 1] = acc[mf][nf][2 * g + 1];
                }
        __syncthreads();

        const int bb = bm >> 11;
        const int s0 = bm & (SEQ - 1);
#pragma unroll
        for (int i = 0; i < 16; i++) {
            int cl = wid * 16 + i;
            int gc = bn + cl;
            int hh = gc >> 6, d = gc & 63;
            float v0 = tile[(lane * 4 + 0) * 130 + cl];
            float v1 = tile[(lane * 4 + 1) * 130 + cl];
            float v2 = tile[(lane * 4 + 2) * 130 + cl];
            float v3 = tile[(lane * 4 + 3) * 130 + cl];
            uint2 hv = make_uint2(pack2bf(v0, v1), pack2bf(v2, v3));
            uint2 lv = make_uint2(
                pack2bf(v0 - bf_round(v0), v1 - bf_round(v1)),
                pack2bf(v2 - bf_round(v2), v3 - bf_round(v3)));
            size_t ob = ((size_t)(bb * NHEADS + hh) * DK + d) * SEQ + s0 + lane * 4;
            *(uint2*)(vthi + ob) = hv;
            *(uint2*)(vtlo + ob) = lv;
        }
        return;
    }

    const float sc = (z == 0) ? SCALE : 1.0f;
    __nv_bfloat16* hi = (z == 0) ? qhi : khi;
    __nv_bfloat16* lo = (z == 0) ? qlo : klo;
#pragma unroll
    for (int mf = 0; mf < 4; mf++)
#pragma unroll
        for (int nf = 0; nf < 4; nf++) {
            const int col = cbase + nf * 8;
            const int fi  = (col & 63) >> 1;
#pragma unroll
            for (int g = 0; g < 2; g++) {
                const int tok = rbase + mf * 16 + g * 8;
                const float2 cs = tab[((tok & (SEQ - 1)) << 5) + fi];
                float e = acc[mf][nf][2 * g], o = acc[mf][nf][2 * g + 1];
                float oe = (e * cs.x - o * cs.y) * sc;
                float oo = (o * cs.x + e * cs.y) * sc;
                store_split2(hi, lo, (size_t)tok * DMODEL + col, oe, oo);
            }
        }
}

// ---------------------------------------------------------------------------
// Output-projection GEMM (2 CTAs/SM): plain fp32 C.
// ---------------------------------------------------------------------------
__global__ __launch_bounds__(256, 2) void gemm_out(
    const __nv_bfloat16* __restrict__ Ahi, const __nv_bfloat16* __restrict__ Alo,
    const __nv_bfloat16* __restrict__ Bhi, const __nv_bfloat16* __restrict__ Blo,
    float* __restrict__ C)
{
    extern __shared__ char smc[];
    const uint32_t sb = smem_to_u32(smc);
    const int tid = threadIdx.x, wid = tid >> 5, lane = tid & 31;
    const int bm = blockIdx.y * 128, bn = blockIdx.x * 128;

    float acc[4][4][4];
    gemm_mainloop(sb, tid, wid, lane, Ahi, Alo, Bhi, Blo, bm, bn, acc);

    const int mwarp = wid & 1, nwarp = wid >> 1;
    const int rbase = bm + mwarp * 64 + (lane >> 2);
    const int cbase = bn + nwarp * 32 + (lane & 3) * 2;
#pragma unroll
    for (int mf = 0; mf < 4; mf++)
#pragma unroll
        for (int nf = 0; nf < 4; nf++) {
            size_t o0 = (size_t)(rbase + mf * 16) * DMODEL + cbase + nf * 8;
            *(float2*)&C[o0]              = make_float2(acc[mf][nf][0], acc[mf][nf][1]);
            *(float2*)&C[o0 + 8 * DMODEL] = make_float2(acc[mf][nf][2], acc[mf][nf][3]);
        }
}

// ---------------------------------------------------------------------------
// Fused operand split
// ---------------------------------------------------------------------------
__global__ void split_all(
    const float* __restrict__ x,
    const float* __restrict__ w0, const float* __restrict__ w1,
    const float* __restrict__ w2, const float* __restrict__ w3,
    __nv_bfloat16* __restrict__ ahi, __nv_bfloat16* __restrict__ alo,
    __nv_bfloat16* __restrict__ whi, __nv_bfloat16* __restrict__ wlo)
{
    const int nx4 = MTOT * DMODEL / 4;
    const int nw4 = WSZ / 4;
    int i = blockIdx.x * blockDim.x + threadIdx.x;

    const float* src;
    __nv_bfloat16 *hi, *lo;
    int r;
    if (i < nx4) {
        src = x; hi = ahi; lo = alo; r = i;
    } else {
        int j = i - nx4;
        int z = j / nw4;
        if (z >= 4) return;
        r = j - z * nw4;
        src = (z == 0) ? w0 : (z == 1) ? w1 : (z == 2) ? w2 : w3;
        hi = whi + (size_t)z * WSZ;
        lo = wlo + (size_t)z * WSZ;
    }

    float4 v = ((const float4*)src)[r];
    __nv_bfloat16 h0 = __float2bfloat16(v.x), h1 = __float2bfloat16(v.y);
    __nv_bfloat16 h2 = __float2bfloat16(v.z), h3 = __float2bfloat16(v.w);
    ((__nv_bfloat162*)hi)[2 * r]     = __nv_bfloat162(h0, h1);
    ((__nv_bfloat162*)hi)[2 * r + 1] = __nv_bfloat162(h2, h3);
    ((__nv_bfloat162*)lo)[2 * r]     = __nv_bfloat162(
        __float2bfloat16(v.x - __bfloat162float(h0)),
        __float2bfloat16(v.y - __bfloat162float(h1)));
    ((__nv_bfloat162*)lo)[2 * r + 1] = __nv_bfloat162(
        __float2bfloat16(v.z - __bfloat162float(h2)),
        __float2bfloat16(v.w - __bfloat162float(h3)));
}

// ---------------------------------------------------------------------------
// RoPE table
// ---------------------------------------------------------------------------
__global__ void rope_table(float2* __restrict__ tab, const int* __restrict__ pos)
{
    int i = blockIdx.x * blockDim.x + threadIdx.x;
    if (i >= SEQ * 32) return;
    int fi = i & 31, s = i >> 5;
    double invf = exp2(-(double)fi * 0.41524101186091903);
    float ang = (float)pos[s] * (float)invf;
    double sd, cd;
    sincos((double)ang, &sd, &cd);
    tab[i] = make_float2((float)cd, (float)sd);
}

// ---------------------------------------------------------------------------
// Tensor-core causal flash attention, software-pipelined:
// QK(kt+1) issued before softmax(kt)+PV(kt) so tensor work overlaps the
// MUFU/SHFL latency chain. 3-stage K/V ring, sf double-buffered via two
// named arrays + 2x-unrolled loop (ktiles always even). 1 CTA/SM.
// ---------------------------------------------------------------------------
#define AQ_MAT      18432u
#define AK_MAT      9216u
#define AT_STRIDE_B 144u
#define AT_SMEM     (2u * AQ_MAT + 12u * AK_MAT)   // 147456 B

__device__ __forceinline__ void attn_issue_tile(
    uint32_t sb, int stage, int s0, int tid, size_t qk_base, size_t vt_base,
    const __nv_bfloat16* Khi, const __nv_bfloat16* Klo,
    const __nv_bfloat16* VThi, const __nv_bfloat16* VTlo)
{
    uint32_t base = sb + 2u * AQ_MAT + (uint32_t)stage * 4u * AK_MAT;
#pragma unroll
    for (int i = 0; i < 2; i++) {
        int c = tid + i * 256, row = c >> 3, seg = c & 7;
        uint32_t so = (uint32_t)row * AT_STRIDE_B + seg * 16;
        cp_async16(base + so,              Khi  + qk_base + (size_t)(s0 + row) * DMODEL + seg * 8);
        cp_async16(base + AK_MAT + so,     Klo  + qk_base + (size_t)(s0 + row) * DMODEL + seg * 8);
        cp_async16(base + 2 * AK_MAT + so, VThi + vt_base + (size_t)row * SEQ + s0 + seg * 8);
        cp_async16(base + 3 * AK_MAT + so, VTlo + vt_base + (size_t)row * SEQ + s0 + seg * 8);
    }
    asm volatile("cp.async.commit_group;" ::: "memory");
}

// QK of one 64-key tile into SF (zero-init included). 3-term bf16x3.
#define ATTN_QK(SF, KBHI, KBLO)                                               \
    {                                                                         \
        _Pragma("unroll")                                                     \
        for (int p = 0; p < 4; p++) {                                         \
            float* s0p = SF[2 * p];                                           \
            float* s1p = SF[2 * p + 1];                                       \
            s0p[0] = s0p[1] = s0p[2] = s0p[3] = 0.f;                          \
            s1p[0] = s1p[1] = s1p[2] = s1p[3] = 0.f;                          \
            _Pragma("unroll")                                                 \
            for (int ks = 0; ks < 4; ks++) {                                  \
                uint32_t off = (uint32_t)(p * 16 + prow) * AT_STRIDE_B        \
                             + (uint32_t)(ks * 16 + psel) * 2;                \
                uint32_t bh4[4], bl4[4];                                      \
                ldsm4(bh4, (KBHI) + off);                                     \
                ldsm4(bl4, (KBLO) + off);                                     \
                mma_bf16(s0p, qh[ks], &bh4[0]);                               \
                mma_bf16(s1p, qh[ks], &bh4[2]);                               \
                mma_bf16(s0p, ql[ks], &bh4[0]);                               \
                mma_bf16(s1p, ql[ks], &bh4[2]);                               \
                mma_bf16(s0p, qh[ks], &bl4[0]);                               \
                mma_bf16(s1p, qh[ks], &bl4[2]);                               \
            }                                                                 \
        }                                                                     \
    }

// softmax + PV of one tile on SF (tile index KT for masking / V stage).
#define ATTN_SMAX_PV(SF, KT, VBHI, VBLO)                                      \
    {                                                                         \
        if ((KT) >= ktiles - 2) {                                             \
            const int kc0 = (KT) * 64 + (lane & 3) * 2;                       \
            _Pragma("unroll")                                                 \
            for (int nf = 0; nf < 8; nf++) {                                  \
                int key = kc0 + nf * 8;                                       \
                if (key     > r0)     SF[nf][0] = -1e30f;                     \
                if (key + 1 > r0)     SF[nf][1] = -1e30f;                     \
                if (key     > r0 + 8) SF[nf][2] = -1e30f;                     \
                if (key + 1 > r0 + 8) SF[nf][3] = -1e30f;                     \
            }                                                                 \
        }                                                                     \
        float mt0 = SF[0][0], mt1 = SF[0][2];                                 \
        _Pragma("unroll")                                                     \
        for (int nf = 0; nf < 8; nf++) {                                      \
            mt0 = fmaxf(mt0, fmaxf(SF[nf][0], SF[nf][1]));                    \
            mt1 = fmaxf(mt1, fmaxf(SF[nf][2], SF[nf][3]));                    \
        }                                                                     \
        mt0 = fmaxf(mt0, __shfl_xor_sync(0xffffffffu, mt0, 1));               \
        mt0 = fmaxf(mt0, __shfl_xor_sync(0xffffffffu, mt0, 2));               \
        mt1 = fmaxf(mt1, __shfl_xor_sync(0xffffffffu, mt1, 1));               \
        mt1 = fmaxf(mt1, __shfl_xor_sync(0xffffffffu, mt1, 2));               \
        float mn0 = fmaxf(m0, mt0), mn1 = fmaxf(m1, mt1);                     \
        float c0 = __expf(m0 - mn0), c1 = __expf(m1 - mn1);                   \
        float lt0 = 0.f, lt1 = 0.f;                                           \
        _Pragma("unroll")                                                     \
        for (int nf = 0; nf < 8; nf++) {                                      \
            SF[nf][0] = __expf(SF[nf][0] - mn0);                              \
            SF[nf][1] = __expf(SF[nf][1] - mn0);                              \
            SF[nf][2] = __expf(SF[nf][2] - mn1);                              \
            SF[nf][3] = __expf(SF[nf][3] - mn1);                              \
            lt0 += SF[nf][0] + SF[nf][1];                                     \
            lt1 += SF[nf][2] + SF[nf][3];                                     \
        }                                                                     \
        lt0 += __shfl_xor_sync(0xffffffffu, lt0, 1);                          \
        lt0 += __shfl_xor_sync(0xffffffffu, lt0, 2);                          \
        lt1 += __shfl_xor_sync(0xffffffffu, lt1, 1);                          \
        lt1 += __shfl_xor_sync(0xffffffffu, lt1, 2);                          \
        l0 = l0 * c0 + lt0;  l1 = l1 * c1 + lt1;                              \
        m0 = mn0;            m1 = mn1;                                        \
        _Pragma("unroll")                                                     \
        for (int nf = 0; nf < 8; nf++) {                                      \
            o_acc[nf][0] *= c0; o_acc[nf][1] *= c0;                           \
            o_acc[nf][2] *= c1; o_acc[nf][3] *= c1;                           \
        }                                                                     \
        _Pragma("unroll")                                                     \
        for (int ks = 0; ks < 4; ks++) {                                      \
            float p00 = SF[2 * ks][0],     p01 = SF[2 * ks][1];               \
            float p02 = SF[2 * ks][2],     p03 = SF[2 * ks][3];               \
            float p10 = SF[2 * ks + 1][0], p11 = SF[2 * ks + 1][1];           \
            float p12 = SF[2 * ks + 1][2], p13 = SF[2 * ks + 1][3];           \
            uint32_t ph[4], pl[4];                                            \
            ph[0] = pack2bf(p00, p01);                                        \
            ph[1] = pack2bf(p02, p03);                                        \
            ph[2] = pack2bf(p10, p11);                                        \
            ph[3] = pack2bf(p12, p13);                                        \
            pl[0] = pack2bf(p00 - bf_round(p00), p01 - bf_round(p01));        \
            pl[1] = pack2bf(p02 - bf_round(p02), p03 - bf_round(p03));        \
            pl[2] = pack2bf(p10 - bf_round(p10), p11 - bf_round(p11));        \
            pl[3] = pack2bf(p12 - bf_round(p12), p13 - bf_round(p13));        \
            _Pragma("unroll")                                                 \
            for (int p = 0; p < 4; p++) {                                     \
                uint32_t off = (uint32_t)(p * 16 + prow) * AT_STRIDE_B        \
                             + (uint32_t)(ks * 16 + psel) * 2;                \
                uint32_t vh4[4], vl4[4];                                      \
                ldsm4(vh4, (VBHI) + off);                                     \
                ldsm4(vl4, (VBLO) + off);                                     \
                mma_bf16(o_acc[2 * p],     ph, &vh4[0]);                      \
                mma_bf16(o_acc[2 * p + 1], ph, &vh4[2]);                      \
                mma_bf16(o_acc[2 * p],     pl, &vh4[0]);                      \
                mma_bf16(o_acc[2 * p + 1], pl, &vh4[2]);                      \
                mma_bf16(o_acc[2 * p],     ph, &vl4[0]);                      \
                mma_bf16(o_acc[2 * p + 1], ph, &vl4[2]);                      \
            }                                                                 \
        }                                                                     \
    }

// One pipeline step: wait tile kt+1, issue tile kt+2, QK(kt+1)->SFN,
// then softmax+PV(kt) on SFC. Entry invariant: QK(kt) already in SFC.
#define ATTN_TILE_STEP(KT, SFC, SFN)                                          \
    {                                                                         \
        asm volatile("cp.async.wait_group 0;" ::: "memory");                  \
        __syncthreads();                                                      \
        if ((KT) + 2 < ktiles)                                                \
            attn_issue_tile(sb, ((KT) + 2) % 3, ((KT) + 2) * 64, tid,         \
                            qk_base, vt_base, Khi, Klo, VThi, VTlo);          \
        if ((KT) + 1 < ktiles && (wid >= 4 || (KT) + 1 < ktiles - 1)) {       \
            const uint32_t nb = sb + 2u * AQ_MAT                              \
                              + (uint32_t)(((KT) + 1) % 3) * 4u * AK_MAT;     \
            ATTN_QK(SFN, nb, nb + AK_MAT);                                    \
        }                                                                     \
        if (!(wid < 4 && (KT) == ktiles - 1)) {                               \
            const uint32_t cb = sb + 2u * AQ_MAT                              \
                              + (uint32_t)((KT) % 3) * 4u * AK_MAT;           \
            ATTN_SMAX_PV(SFC, (KT), cb + 2u * AK_MAT, cb + 3u * AK_MAT);      \
        }                                                                     \
    }

__global__ __launch_bounds__(256, 1) void attn_mma(
    const __nv_bfloat16* __restrict__ Qhi, const __nv_bfloat16* __restrict__ Qlo,
    const __nv_bfloat16* __restrict__ Khi, const __nv_bfloat16* __restrict__ Klo,
    const __nv_bfloat16* __restrict__ VThi, const __nv_bfloat16* __restrict__ VTlo,
    __nv_bfloat16* __restrict__ Ohi, __nv_bfloat16* __restrict__ Olo)
{
    extern __shared__ char smc[];
    const uint32_t sb = smem_to_u32(smc);
    const int tid = threadIdx.x, wid = tid >> 5, lane = tid & 31;
    const int b = blockIdx.z, h = blockIdx.y;
    const int q0 = (gridDim.x - 1 - blockIdx.x) * 128;

    const size_t qk_base = (size_t)b * SEQ * DMODEL + (size_t)h * DK;
    const size_t vt_base = ((size_t)(b * NHEADS + h)) * DK * SEQ;

    // Q load (group) then K/V tiles 0 and 1 (groups)
#pragma unroll
    for (int i = 0; i < 4; i++) {
        int c = tid + i * 256, row = c >> 3, seg = c & 7;
        uint32_t so = (uint32_t)row * AT_STRIDE_B + seg * 16;
        cp_async16(sb + so,          Qhi + qk_base + (size_t)(q0 + row) * DMODEL + seg * 8);
        cp_async16(sb + AQ_MAT + so, Qlo + qk_base + (size_t)(q0 + row) * DMODEL + seg * 8);
    }
    asm volatile("cp.async.commit_group;" ::: "memory");

    const int ktiles = (q0 >> 6) + 2;   // always even (q0 multiple of 128)
    attn_issue_tile(sb, 0, 0,  tid, qk_base, vt_base, Khi, Klo, VThi, VTlo);
    attn_issue_tile(sb, 1, 64, tid, qk_base, vt_base, Khi, Klo, VThi, VTlo);

    // Q fragments (register-resident)
    asm volatile("cp.async.wait_group 2;" ::: "memory");   // Q done
    __syncthreads();
    uint32_t qh[4][4], ql[4][4];
    {
        const int arow = wid * 16 + (lane & 7) + ((lane >> 3) & 1) * 8;
#pragma unroll
        for (int ks = 0; ks < 4; ks++) {
            uint32_t off = (uint32_t)arow * AT_STRIDE_B + (uint32_t)(ks * 16 + (lane >> 4) * 8) * 2;
            ldsm4(qh[ks], sb + off);
            ldsm4(ql[ks], sb + AQ_MAT + off);
        }
    }

    float o_acc[8][4];
#pragma unroll
    for (int nf = 0; nf < 8; nf++)
#pragma unroll
        for (int e = 0; e < 4; e++) o_acc[nf][e] = 0.f;
    float m0 = -INFINITY, m1 = -INFINITY, l0 = 0.f, l1 = 0.f;

    const int prow = ((lane >> 4) & 1) * 8 + (lane & 7);
    const int psel = ((lane >> 3) & 1) * 8;
    const int r0 = q0 + wid * 16 + (lane >> 2);

    float sfA[8][4], sfB[8][4];

    // Prologue: QK(0) -> sfA  (wait tile 0, leave tile 1 pending)
    asm volatile("cp.async.wait_group 1;" ::: "memory");
    __syncthreads();
    {
        const uint32_t kb0 = sb + 2u * AQ_MAT;   // stage 0
        ATTN_QK(sfA, kb0, kb0 + AK_MAT);
    }

    // Pipelined mainloop, 2 tiles per iteration (ktiles even)
    for (int kt = 0; kt < ktiles; kt += 2) {
        ATTN_TILE_STEP(kt,     sfA, sfB);
        ATTN_TILE_STEP(kt + 1, sfB, sfA);
    }

    const float inv0 = 1.f / l0, inv1 = 1.f / l1;
#pragma unroll
    for (int nf = 0; nf < 8; nf++) {
        int col = nf * 8 + (lane & 3) * 2;
        store_split2(Ohi, Olo, qk_base + (size_t)r0 * DMODEL + col,
                     o_acc[nf][0] * inv0, o_acc[nf][1] * inv0);
        store_split2(Ohi, Olo, qk_base + (size_t)(r0 + 8) * DMODEL + col,
                     o_acc[nf][2] * inv1, o_acc[nf][3] * inv1);
    }
}

// ---------------------------------------------------------------------------
// Launch
// ---------------------------------------------------------------------------
extern "C" void kernel_launch(void* const* d_in, const int* in_sizes, int n_in,
                              void* d_out, int out_size)
{
    const float* x  = (const float*)d_in[0];
    const float* Wq = (const float*)d_in[1];
    const float* Wk = (const float*)d_in[2];
    const float* Wv = (const float*)d_in[3];
    const float* Wo = (const float*)d_in[4];
    const int*   tp = (const int*)d_in[5];
    float* out = (float*)d_out;

    __nv_bfloat16 *ahi, *alo, *whi, *wlo, *qhi, *qlo, *khi, *klo, *vthi, *vtlo;
    float2* cs;
    cudaGetSymbolAddress((void**)&ahi,  g_ahi);
    cudaGetSymbolAddress((void**)&alo,  g_alo);
    cudaGetSymbolAddress((void**)&whi,  g_whi);
    cudaGetSymbolAddress((void**)&wlo,  g_wlo);
    cudaGetSymbolAddress((void**)&qhi,  g_qhi);
    cudaGetSymbolAddress((void**)&qlo,  g_qlo);
    cudaGetSymbolAddress((void**)&khi,  g_khi);
    cudaGetSymbolAddress((void**)&klo,  g_klo);
    cudaGetSymbolAddress((void**)&vthi, g_vthi);
    cudaGetSymbolAddress((void**)&vtlo, g_vtlo);
    cudaGetSymbolAddress((void**)&cs,   g_cs);

    cudaFuncSetAttribute(gemm_qkv, cudaFuncAttributeMaxDynamicSharedMemorySize, GEMM_SMEM);
    cudaFuncSetAttribute(gemm_out, cudaFuncAttributeMaxDynamicSharedMemorySize, GEMM_SMEM);
    cudaFuncSetAttribute(attn_mma, cudaFuncAttributeMaxDynamicSharedMemorySize, AT_SMEM);

    const int nsplit = MTOT * DMODEL / 4 + WSZ;

    split_all<<<(nsplit + 255) / 256, 256>>>(x, Wq, Wk, Wv, Wo, ahi, alo, whi, wlo);
    rope_table<<<(SEQ * 32 + 255) / 256, 256>>>(cs, tp);

    gemm_qkv<<<dim3(DMODEL / 128, MTOT / 128, 3), 256, GEMM_SMEM>>>(
        ahi, alo, whi, wlo, qhi, qlo, khi, klo, vthi, vtlo, cs);

    attn_mma<<<dim3(SEQ / 128, NHEADS, BATCH), 256, AT_SMEM>>>(
        qhi, qlo, khi, klo, vthi, vtlo, ahi, alo);

    gemm_out<<<dim3(DMODEL / 128, MTOT / 128), 256, GEMM_SMEM>>>(
        ahi, alo, whi + (size_t)3 * WSZ, wlo + (size_t)3 * WSZ, out);
}

// round 14
// speedup vs baseline: 1.0178x; 1.0178x over previous
#include <cuda_runtime.h>
#include <cuda_bf16.h>
#include <math.h>
#include <stdint.h>

// ---------------------------------------------------------------------------
// Problem constants
// ---------------------------------------------------------------------------
#define BATCH   2
#define SEQ     2048
#define DMODEL  1024
#define NHEADS  16
#define DK      64
#define MTOT    (BATCH * SEQ)        // 4096
#define SCALE   0.125f               // 1/sqrt(64)
#define WSZ     (DMODEL * DMODEL)

// ---------------------------------------------------------------------------
// Scratch (__device__ globals; allocation-free rule)
// ---------------------------------------------------------------------------
__device__ __nv_bfloat16 g_ahi[MTOT * DMODEL];
__device__ __nv_bfloat16 g_alo[MTOT * DMODEL];
__device__ __nv_bfloat16 g_whi[4 * WSZ];
__device__ __nv_bfloat16 g_wlo[4 * WSZ];
__device__ __nv_bfloat16 g_qhi[MTOT * DMODEL];
__device__ __nv_bfloat16 g_qlo[MTOT * DMODEL];
__device__ __nv_bfloat16 g_khi[MTOT * DMODEL];
__device__ __nv_bfloat16 g_klo[MTOT * DMODEL];
__device__ __nv_bfloat16 g_vthi[MTOT * DMODEL];
__device__ __nv_bfloat16 g_vtlo[MTOT * DMODEL];
__device__ float2 g_cs[SEQ * (DK / 2)];

// ---------------------------------------------------------------------------
// PTX helpers
// ---------------------------------------------------------------------------
__device__ __forceinline__ uint32_t smem_to_u32(const void* p) {
    uint32_t a;
    asm("{ .reg .u64 t; cvta.to.shared.u64 t, %1; cvt.u32.u64 %0, t; }"
        : "=r"(a) : "l"(p));
    return a;
}

__device__ __forceinline__ void cp_async16(uint32_t dst, const void* src) {
    asm volatile("cp.async.cg.shared.global [%0], [%1], 16;" :: "r"(dst), "l"(src));
}

__device__ __forceinline__ void ldsm4(uint32_t* r, uint32_t addr) {
    asm volatile("ldmatrix.sync.aligned.m8n8.x4.shared.b16 {%0,%1,%2,%3}, [%4];"
                 : "=r"(r[0]), "=r"(r[1]), "=r"(r[2]), "=r"(r[3]) : "r"(addr));
}

__device__ __forceinline__ void mma_bf16(float* d, const uint32_t* a, const uint32_t* b) {
    asm volatile(
        "mma.sync.aligned.m16n8k16.row.col.f32.bf16.bf16.f32 "
        "{%0,%1,%2,%3}, {%4,%5,%6,%7}, {%8,%9}, {%0,%1,%2,%3};"
        : "+f"(d[0]), "+f"(d[1]), "+f"(d[2]), "+f"(d[3])
        : "r"(a[0]), "r"(a[1]), "r"(a[2]), "r"(a[3]), "r"(b[0]), "r"(b[1]));
}

__device__ __forceinline__ uint32_t pack2bf(float a, float b) {
    __nv_bfloat162 t = __floats2bfloat162_rn(a, b);
    return *reinterpret_cast<uint32_t*>(&t);
}
__device__ __forceinline__ float bf_round(float x) {
    return __bfloat162float(__float2bfloat16(x));
}
__device__ __forceinline__ void store_split2(
    __nv_bfloat16* hi, __nv_bfloat16* lo, size_t off, float a, float b)
{
    __nv_bfloat16 ha = __float2bfloat16(a), hb = __float2bfloat16(b);
    *(__nv_bfloat162*)(hi + off) = __nv_bfloat162(ha, hb);
    *(__nv_bfloat162*)(lo + off) = __nv_bfloat162(
        __float2bfloat16(a - __bfloat162float(ha)),
        __float2bfloat16(b - __bfloat162float(hb)));
}

// ---------------------------------------------------------------------------
// GEMM mainloop (NT, bf16x3, 128x128 tile, BK=32, 3-stage cp.async,
// SW64-swizzled unpadded 64B-row smem, single barrier per chunk).
// ---------------------------------------------------------------------------
#define MAT_B   8192u
#define STAGE_B 32768u
#define GEMM_SMEM (3 * STAGE_B)

__device__ __forceinline__ uint32_t sw64(int row, int seg) {
    return (uint32_t)(row * 64 + ((seg ^ ((row >> 1) & 3)) << 4));
}

__device__ __forceinline__ void gemm_issue(
    uint32_t dstHi, uint32_t dstLo,
    const __nv_bfloat16* srcHi, const __nv_bfloat16* srcLo, int t, int k0)
{
#pragma unroll
    for (int i = 0; i < 4; i++) {
        int chunk = t + (i << 7);
        int row = chunk >> 2, seg = chunk & 3;
        uint32_t so = sw64(row, seg);
        const size_t go = (size_t)row * DMODEL + k0 + seg * 8;
        cp_async16(dstHi + so, srcHi + go);
        cp_async16(dstLo + so, srcLo + go);
    }
    asm volatile("cp.async.commit_group;" ::: "memory");
}

__device__ __forceinline__ void gemm_mainloop(
    uint32_t sb, int tid, int wid, int lane,
    const __nv_bfloat16* __restrict__ Ahi, const __nv_bfloat16* __restrict__ Alo,
    const __nv_bfloat16* __restrict__ Bhi, const __nv_bfloat16* __restrict__ Blo,
    int bm, int bn, float acc[4][4][4])
{
    const bool isA = tid < 128;
    const int t = isA ? tid : tid - 128;
    const __nv_bfloat16* srcHi = isA ? (Ahi + (size_t)bm * DMODEL)
                                     : (Bhi + (size_t)bn * DMODEL);
    const __nv_bfloat16* srcLo = isA ? (Alo + (size_t)bm * DMODEL)
                                     : (Blo + (size_t)bn * DMODEL);
    const uint32_t matHiOff = isA ? 0u : 2u * MAT_B;
    const uint32_t matLoOff = matHiOff + MAT_B;

#pragma unroll
    for (int i = 0; i < 4; i++)
#pragma unroll
        for (int j = 0; j < 4; j++)
#pragma unroll
            for (int e = 0; e < 4; e++) acc[i][j][e] = 0.f;

    const int mwarp = wid & 1, nwarp = wid >> 1;

    const int arowb = mwarp * 64 + (lane & 7) + ((lane >> 3) & 1) * 8;
    const int asegb = (lane >> 4) & 1;
    const int browb = nwarp * 32 + ((lane >> 4) & 1) * 8 + (lane & 7);
    const int bsegb = (lane >> 3) & 1;

    gemm_issue(sb + matHiOff, sb + matLoOff, srcHi, srcLo, t, 0);
    gemm_issue(sb + STAGE_B + matHiOff, sb + STAGE_B + matLoOff, srcHi, srcLo, t, 32);

    for (int c = 0; c < 32; c++) {
        if (c < 31) asm volatile("cp.async.wait_group 1;" ::: "memory");
        else        asm volatile("cp.async.wait_group 0;" ::: "memory");
        __syncthreads();

        if (c + 2 < 32) {
            const uint32_t base = sb + (uint32_t)((c + 2) % 3) * STAGE_B;
            gemm_issue(base + matHiOff, base + matLoOff, srcHi, srcLo, t, (c + 2) * 32);
        }

        const uint32_t stg = sb + (uint32_t)(c % 3) * STAGE_B;
        const uint32_t aHi = stg, aLo = stg + MAT_B;
        const uint32_t bHi = stg + 2u * MAT_B, bLo = stg + 3u * MAT_B;

#pragma unroll
        for (int ks = 0; ks < 2; ks++) {
            const int segA = ks * 2 + asegb;
            const int segB = ks * 2 + bsegb;

            uint32_t af[4][4], bh[2][4], bl[2][4];
#pragma unroll
            for (int mf = 0; mf < 4; mf++) {
                int row = arowb + mf * 16;
                ldsm4(af[mf], aHi + sw64(row, segA));
            }
#pragma unroll
            for (int p = 0; p < 2; p++) {
                int row = browb + p * 16;
                uint32_t off = sw64(row, segB);
                ldsm4(bh[p], bHi + off);
                ldsm4(bl[p], bLo + off);
            }
#pragma unroll
            for (int mf = 0; mf < 4; mf++)
#pragma unroll
                for (int p = 0; p < 2; p++) {
                    mma_bf16(acc[mf][2 * p],     af[mf], &bh[p][0]);
                    mma_bf16(acc[mf][2 * p + 1], af[mf], &bh[p][2]);
                }
#pragma unroll
            for (int mf = 0; mf < 4; mf++)
#pragma unroll
                for (int p = 0; p < 2; p++) {
                    mma_bf16(acc[mf][2 * p],     af[mf], &bl[p][0]);
                    mma_bf16(acc[mf][2 * p + 1], af[mf], &bl[p][2]);
                }
            uint32_t alf[4][4];
#pragma unroll
            for (int mf = 0; mf < 4; mf++) {
                int row = arowb + mf * 16;
                ldsm4(alf[mf], aLo + sw64(row, segA));
            }
#pragma unroll
            for (int mf = 0; mf < 4; mf++)
#pragma unroll
                for (int p = 0; p < 2; p++) {
                    mma_bf16(acc[mf][2 * p],     alf[mf], &bh[p][0]);
                    mma_bf16(acc[mf][2 * p + 1], alf[mf], &bh[p][2]);
                }
        }
    }
}

// ---------------------------------------------------------------------------
// QKV GEMM (2 CTAs/SM): z=0 Q (rope+scale+split), z=1 K (rope+split),
// z=2 V (transpose + split fused via smem staging -> vthi/vtlo directly).
// ---------------------------------------------------------------------------
__global__ __launch_bounds__(256, 2) void gemm_qkv(
    const __nv_bfloat16* __restrict__ Ahi, const __nv_bfloat16* __restrict__ Alo,
    const __nv_bfloat16* __restrict__ Whi, const __nv_bfloat16* __restrict__ Wlo,
    __nv_bfloat16* __restrict__ qhi, __nv_bfloat16* __restrict__ qlo,
    __nv_bfloat16* __restrict__ khi, __nv_bfloat16* __restrict__ klo,
    __nv_bfloat16* __restrict__ vthi, __nv_bfloat16* __restrict__ vtlo,
    const float2* __restrict__ tab)
{
    extern __shared__ char smc[];
    const uint32_t sb = smem_to_u32(smc);
    const int tid = threadIdx.x, wid = tid >> 5, lane = tid & 31;
    const int bm = blockIdx.y * 128, bn = blockIdx.x * 128;
    const int z = blockIdx.z;

    float acc[4][4][4];
    gemm_mainloop(sb, tid, wid, lane, Ahi, Alo,
                  Whi + (size_t)z * WSZ, Wlo + (size_t)z * WSZ, bm, bn, acc);

    const int mwarp = wid & 1, nwarp = wid >> 1;
    const int rbase = bm + mwarp * 64 + (lane >> 2);
    const int cbase = bn + nwarp * 32 + (lane & 3) * 2;

    if (z == 2) {
        float* tile = (float*)smc;               // 128 x 130 fp32
        __syncthreads();
#pragma unroll
        for (int mf = 0; mf < 4; mf++)
#pragma unroll
            for (int nf = 0; nf < 4; nf++)
#pragma unroll
                for (int g = 0; g < 2; g++) {
                    int rl = mwarp * 64 + (lane >> 2) + mf * 16 + g * 8;
                    int cl = nwarp * 32 + (lane & 3) * 2 + nf * 8;
                    tile[rl * 130 + cl]     = acc[mf][nf][2 * g];
                    tile[rl * 130 + cl + 1] = acc[mf][nf][2 * g + 1];
                }
        __syncthreads();

        const int bb = bm >> 11;
        const int s0 = bm & (SEQ - 1);
#pragma unroll
        for (int i = 0; i < 16; i++) {
            int cl = wid * 16 + i;
            int gc = bn + cl;
            int hh = gc >> 6, d = gc & 63;
            float v0 = tile[(lane * 4 + 0) * 130 + cl];
            float v1 = tile[(lane * 4 + 1) * 130 + cl];
            float v2 = tile[(lane * 4 + 2) * 130 + cl];
            float v3 = tile[(lane * 4 + 3) * 130 + cl];
            uint2 hv = make_uint2(pack2bf(v0, v1), pack2bf(v2, v3));
            uint2 lv = make_uint2(
                pack2bf(v0 - bf_round(v0), v1 - bf_round(v1)),
                pack2bf(v2 - bf_round(v2), v3 - bf_round(v3)));
            size_t ob = ((size_t)(bb * NHEADS + hh) * DK + d) * SEQ + s0 + lane * 4;
            *(uint2*)(vthi + ob) = hv;
            *(uint2*)(vtlo + ob) = lv;
        }
        return;
    }

    const float sc = (z == 0) ? SCALE : 1.0f;
    __nv_bfloat16* hi = (z == 0) ? qhi : khi;
    __nv_bfloat16* lo = (z == 0) ? qlo : klo;
#pragma unroll
    for (int mf = 0; mf < 4; mf++)
#pragma unroll
        for (int nf = 0; nf < 4; nf++) {
            const int col = cbase + nf * 8;
            const int fi  = (col & 63) >> 1;
#pragma unroll
            for (int g = 0; g < 2; g++) {
                const int tok = rbase + mf * 16 + g * 8;
                const float2 cs = tab[((tok & (SEQ - 1)) << 5) + fi];
                float e = acc[mf][nf][2 * g], o = acc[mf][nf][2 * g + 1];
                float oe = (e * cs.x - o * cs.y) * sc;
                float oo = (o * cs.x + e * cs.y) * sc;
                store_split2(hi, lo, (size_t)tok * DMODEL + col, oe, oo);
            }
        }
}

// ---------------------------------------------------------------------------
// Output-projection GEMM (2 CTAs/SM): plain fp32 C.
// ---------------------------------------------------------------------------
__global__ __launch_bounds__(256, 2) void gemm_out(
    const __nv_bfloat16* __restrict__ Ahi, const __nv_bfloat16* __restrict__ Alo,
    const __nv_bfloat16* __restrict__ Bhi, const __nv_bfloat16* __restrict__ Blo,
    float* __restrict__ C)
{
    extern __shared__ char smc[];
    const uint32_t sb = smem_to_u32(smc);
    const int tid = threadIdx.x, wid = tid >> 5, lane = tid & 31;
    const int bm = blockIdx.y * 128, bn = blockIdx.x * 128;

    float acc[4][4][4];
    gemm_mainloop(sb, tid, wid, lane, Ahi, Alo, Bhi, Blo, bm, bn, acc);

    const int mwarp = wid & 1, nwarp = wid >> 1;
    const int rbase = bm + mwarp * 64 + (lane >> 2);
    const int cbase = bn + nwarp * 32 + (lane & 3) * 2;
#pragma unroll
    for (int mf = 0; mf < 4; mf++)
#pragma unroll
        for (int nf = 0; nf < 4; nf++) {
            size_t o0 = (size_t)(rbase + mf * 16) * DMODEL + cbase + nf * 8;
            *(float2*)&C[o0]              = make_float2(acc[mf][nf][0], acc[mf][nf][1]);
            *(float2*)&C[o0 + 8 * DMODEL] = make_float2(acc[mf][nf][2], acc[mf][nf][3]);
        }
}

// ---------------------------------------------------------------------------
// Fused operand split
// ---------------------------------------------------------------------------
__global__ void split_all(
    const float* __restrict__ x,
    const float* __restrict__ w0, const float* __restrict__ w1,
    const float* __restrict__ w2, const float* __restrict__ w3,
    __nv_bfloat16* __restrict__ ahi, __nv_bfloat16* __restrict__ alo,
    __nv_bfloat16* __restrict__ whi, __nv_bfloat16* __restrict__ wlo)
{
    const int nx4 = MTOT * DMODEL / 4;
    const int nw4 = WSZ / 4;
    int i = blockIdx.x * blockDim.x + threadIdx.x;

    const float* src;
    __nv_bfloat16 *hi, *lo;
    int r;
    if (i < nx4) {
        src = x; hi = ahi; lo = alo; r = i;
    } else {
        int j = i - nx4;
        int z = j / nw4;
        if (z >= 4) return;
        r = j - z * nw4;
        src = (z == 0) ? w0 : (z == 1) ? w1 : (z == 2) ? w2 : w3;
        hi = whi + (size_t)z * WSZ;
        lo = wlo + (size_t)z * WSZ;
    }

    float4 v = ((const float4*)src)[r];
    __nv_bfloat16 h0 = __float2bfloat16(v.x), h1 = __float2bfloat16(v.y);
    __nv_bfloat16 h2 = __float2bfloat16(v.z), h3 = __float2bfloat16(v.w);
    ((__nv_bfloat162*)hi)[2 * r]     = __nv_bfloat162(h0, h1);
    ((__nv_bfloat162*)hi)[2 * r + 1] = __nv_bfloat162(h2, h3);
    ((__nv_bfloat162*)lo)[2 * r]     = __nv_bfloat162(
        __float2bfloat16(v.x - __bfloat162float(h0)),
        __float2bfloat16(v.y - __bfloat162float(h1)));
    ((__nv_bfloat162*)lo)[2 * r + 1] = __nv_bfloat162(
        __float2bfloat16(v.z - __bfloat162float(h2)),
        __float2bfloat16(v.w - __bfloat162float(h3)));
}

// ---------------------------------------------------------------------------
// RoPE table
// ---------------------------------------------------------------------------
__global__ void rope_table(float2* __restrict__ tab, const int* __restrict__ pos)
{
    int i = blockIdx.x * blockDim.x + threadIdx.x;
    if (i >= SEQ * 32) return;
    int fi = i & 31, s = i >> 5;
    double invf = exp2(-(double)fi * 0.41524101186091903);
    float ang = (float)pos[s] * (float)invf;
    double sd, cd;
    sincos((double)ang, &sd, &cd);
    tab[i] = make_float2((float)cd, (float)sd);
}

// ---------------------------------------------------------------------------
// Tensor-core causal flash attention, 128-KEY TILES:
// halves per-tile fixed costs (barriers, shuffle reductions, o_acc rescale,
// m/l updates) relative to 64-key tiles. Q frags register-resident,
// double-buffered K/V tiles, 1 CTA/SM.
// K tile: 128 keys x 144B (dk-major). VT tile: 64 d x 272B (key-major).
// ---------------------------------------------------------------------------
#define AQ_MAT      18432u           // 128 x 144
#define AK_MAT      18432u           // 128 keys x 144B
#define AV_MAT      17408u           // 64 d x 272B
#define AK_STRIDE   144u
#define AV_STRIDE   272u
#define AT_STAGE    (2u * AK_MAT + 2u * AV_MAT)   // 71680
#define AT_SMEM     (2u * AQ_MAT + 2u * AT_STAGE) // 180224

__device__ __forceinline__ void attn_issue_tile(
    uint32_t sb, int stage, int s0, int tid, size_t qk_base, size_t vt_base,
    const __nv_bfloat16* Khi, const __nv_bfloat16* Klo,
    const __nv_bfloat16* VThi, const __nv_bfloat16* VTlo)
{
    uint32_t base = sb + 2u * AQ_MAT + (uint32_t)stage * AT_STAGE;
#pragma unroll
    for (int i = 0; i < 4; i++) {
        int c = tid + i * 256;               // 0..1023
        int krow = c >> 3, kseg = c & 7;     // K: 128 rows x 8 segs
        uint32_t kso = (uint32_t)krow * AK_STRIDE + kseg * 16;
        cp_async16(base + kso,          Khi + qk_base + (size_t)(s0 + krow) * DMODEL + kseg * 8);
        cp_async16(base + AK_MAT + kso, Klo + qk_base + (size_t)(s0 + krow) * DMODEL + kseg * 8);
        int vrow = c >> 4, vseg = c & 15;    // VT: 64 rows x 16 segs
        uint32_t vso = (uint32_t)vrow * AV_STRIDE + vseg * 16;
        cp_async16(base + 2u * AK_MAT + vso,
                   VThi + vt_base + (size_t)vrow * SEQ + s0 + vseg * 8);
        cp_async16(base + 2u * AK_MAT + AV_MAT + vso,
                   VTlo + vt_base + (size_t)vrow * SEQ + s0 + vseg * 8);
    }
    asm volatile("cp.async.commit_group;" ::: "memory");
}

__global__ __launch_bounds__(256, 1) void attn_mma(
    const __nv_bfloat16* __restrict__ Qhi, const __nv_bfloat16* __restrict__ Qlo,
    const __nv_bfloat16* __restrict__ Khi, const __nv_bfloat16* __restrict__ Klo,
    const __nv_bfloat16* __restrict__ VThi, const __nv_bfloat16* __restrict__ VTlo,
    __nv_bfloat16* __restrict__ Ohi, __nv_bfloat16* __restrict__ Olo)
{
    extern __shared__ char smc[];
    const uint32_t sb = smem_to_u32(smc);
    const int tid = threadIdx.x, wid = tid >> 5, lane = tid & 31;
    const int b = blockIdx.z, h = blockIdx.y;
    const int q0 = (gridDim.x - 1 - blockIdx.x) * 128;   // heavy CTAs first

    const size_t qk_base = (size_t)b * SEQ * DMODEL + (size_t)h * DK;
    const size_t vt_base = ((size_t)(b * NHEADS + h)) * DK * SEQ;

    // Q load then K/V tile 0
#pragma unroll
    for (int i = 0; i < 4; i++) {
        int c = tid + i * 256, row = c >> 3, seg = c & 7;
        uint32_t so = (uint32_t)row * AK_STRIDE + seg * 16;
        cp_async16(sb + so,          Qhi + qk_base + (size_t)(q0 + row) * DMODEL + seg * 8);
        cp_async16(sb + AQ_MAT + so, Qlo + qk_base + (size_t)(q0 + row) * DMODEL + seg * 8);
    }
    asm volatile("cp.async.commit_group;" ::: "memory");

    const int ktiles = (q0 >> 7) + 1;    // 128-key tiles
    attn_issue_tile(sb, 0, 0, tid, qk_base, vt_base, Khi, Klo, VThi, VTlo);

    asm volatile("cp.async.wait_group 1;" ::: "memory");   // Q done
    __syncthreads();

    uint32_t qh[4][4], ql[4][4];
    {
        const int arow = wid * 16 + (lane & 7) + ((lane >> 3) & 1) * 8;
#pragma unroll
        for (int ks = 0; ks < 4; ks++) {
            uint32_t off = (uint32_t)arow * AK_STRIDE + (uint32_t)(ks * 16 + (lane >> 4) * 8) * 2;
            ldsm4(qh[ks], sb + off);
            ldsm4(ql[ks], sb + AQ_MAT + off);
        }
    }

    float o_acc[8][4];
#pragma unroll
    for (int nf = 0; nf < 8; nf++)
#pragma unroll
        for (int e = 0; e < 4; e++) o_acc[nf][e] = 0.f;
    float m0 = -INFINITY, m1 = -INFINITY, l0 = 0.f, l1 = 0.f;

    const int prow = ((lane >> 4) & 1) * 8 + (lane & 7);
    const int psel = ((lane >> 3) & 1) * 8;
    const int r0 = q0 + wid * 16 + (lane >> 2);

    for (int kt = 0; kt < ktiles; kt++) {
        asm volatile("cp.async.wait_group 0;" ::: "memory");
        __syncthreads();
        if (kt + 1 < ktiles)
            attn_issue_tile(sb, (kt + 1) & 1, (kt + 1) * 128, tid, qk_base, vt_base,
                            Khi, Klo, VThi, VTlo);

        const uint32_t kb = sb + 2u * AQ_MAT + (uint32_t)(kt & 1) * AT_STAGE;
        const uint32_t kb_lo = kb + AK_MAT;
        const uint32_t vb_hi = kb + 2u * AK_MAT;
        const uint32_t vb_lo = vb_hi + AV_MAT;

        // ---- S = Q K^T (bf16x3), 16 key-fragments via 8 paired ldsm4 ----
        float sf[16][4];
#pragma unroll
        for (int p = 0; p < 8; p++) {
            float* s0p = sf[2 * p];
            float* s1p = sf[2 * p + 1];
            s0p[0] = s0p[1] = s0p[2] = s0p[3] = 0.f;
            s1p[0] = s1p[1] = s1p[2] = s1p[3] = 0.f;
#pragma unroll
            for (int ks = 0; ks < 4; ks++) {
                uint32_t off = (uint32_t)(p * 16 + prow) * AK_STRIDE
                             + (uint32_t)(ks * 16 + psel) * 2;
                uint32_t bh4[4], bl4[4];
                ldsm4(bh4, kb + off);
                ldsm4(bl4, kb_lo + off);
                mma_bf16(s0p, qh[ks], &bh4[0]);
                mma_bf16(s1p, qh[ks], &bh4[2]);
                mma_bf16(s0p, ql[ks], &bh4[0]);
                mma_bf16(s1p, ql[ks], &bh4[2]);
                mma_bf16(s0p, qh[ks], &bl4[0]);
                mma_bf16(s1p, qh[ks], &bl4[2]);
            }
        }

        // ---- causal mask (final tile contains the diagonal) ----
        if (kt == ktiles - 1) {
            const int kc0 = kt * 128 + (lane & 3) * 2;
#pragma unroll
            for (int nf = 0; nf < 16; nf++) {
                int key = kc0 + nf * 8;
                if (key     > r0)     sf[nf][0] = -1e30f;
                if (key + 1 > r0)     sf[nf][1] = -1e30f;
                if (key     > r0 + 8) sf[nf][2] = -1e30f;
                if (key + 1 > r0 + 8) sf[nf][3] = -1e30f;
            }
        }

        // ---- online softmax over 128 keys ----
        float mt0 = sf[0][0], mt1 = sf[0][2];
#pragma unroll
        for (int nf = 0; nf < 16; nf++) {
            mt0 = fmaxf(mt0, fmaxf(sf[nf][0], sf[nf][1]));
            mt1 = fmaxf(mt1, fmaxf(sf[nf][2], sf[nf][3]));
        }
        mt0 = fmaxf(mt0, __shfl_xor_sync(0xffffffffu, mt0, 1));
        mt0 = fmaxf(mt0, __shfl_xor_sync(0xffffffffu, mt0, 2));
        mt1 = fmaxf(mt1, __shfl_xor_sync(0xffffffffu, mt1, 1));
        mt1 = fmaxf(mt1, __shfl_xor_sync(0xffffffffu, mt1, 2));

        float mn0 = fmaxf(m0, mt0), mn1 = fmaxf(m1, mt1);
        float c0 = __expf(m0 - mn0), c1 = __expf(m1 - mn1);

        float lt0 = 0.f, lt1 = 0.f;
#pragma unroll
        for (int nf = 0; nf < 16; nf++) {
            sf[nf][0] = __expf(sf[nf][0] - mn0);
            sf[nf][1] = __expf(sf[nf][1] - mn0);
            sf[nf][2] = __expf(sf[nf][2] - mn1);
            sf[nf][3] = __expf(sf[nf][3] - mn1);
            lt0 += sf[nf][0] + sf[nf][1];
            lt1 += sf[nf][2] + sf[nf][3];
        }
        lt0 += __shfl_xor_sync(0xffffffffu, lt0, 1);
        lt0 += __shfl_xor_sync(0xffffffffu, lt0, 2);
        lt1 += __shfl_xor_sync(0xffffffffu, lt1, 1);
        lt1 += __shfl_xor_sync(0xffffffffu, lt1, 2);

        l0 = l0 * c0 + lt0;  l1 = l1 * c1 + lt1;
        m0 = mn0;            m1 = mn1;

#pragma unroll
        for (int nf = 0; nf < 8; nf++) {
            o_acc[nf][0] *= c0; o_acc[nf][1] *= c0;
            o_acc[nf][2] *= c1; o_acc[nf][3] *= c1;
        }

        // ---- O += P V (bf16x3), 8 key-groups, paired ldsm4 for V frags ----
#pragma unroll
        for (int ks = 0; ks < 8; ks++) {
            float p00 = sf[2 * ks][0],     p01 = sf[2 * ks][1];
            float p02 = sf[2 * ks][2],     p03 = sf[2 * ks][3];
            float p10 = sf[2 * ks + 1][0], p11 = sf[2 * ks + 1][1];
            float p12 = sf[2 * ks + 1][2], p13 = sf[2 * ks + 1][3];
            uint32_t ph[4], pl[4];
            ph[0] = pack2bf(p00, p01);
            ph[1] = pack2bf(p02, p03);
            ph[2] = pack2bf(p10, p11);
            ph[3] = pack2bf(p12, p13);
            pl[0] = pack2bf(p00 - bf_round(p00), p01 - bf_round(p01));
            pl[1] = pack2bf(p02 - bf_round(p02), p03 - bf_round(p03));
            pl[2] = pack2bf(p10 - bf_round(p10), p11 - bf_round(p11));
            pl[3] = pack2bf(p12 - bf_round(p12), p13 - bf_round(p13));
#pragma unroll
            for (int p = 0; p < 4; p++) {
                uint32_t off = (uint32_t)(p * 16 + prow) * AV_STRIDE
                             + (uint32_t)(ks * 16 + psel) * 2;
                uint32_t vh4[4], vl4[4];
                ldsm4(vh4, vb_hi + off);
                ldsm4(vl4, vb_lo + off);
                mma_bf16(o_acc[2 * p],     ph, &vh4[0]);
                mma_bf16(o_acc[2 * p + 1], ph, &vh4[2]);
                mma_bf16(o_acc[2 * p],     pl, &vh4[0]);
                mma_bf16(o_acc[2 * p + 1], pl, &vh4[2]);
                mma_bf16(o_acc[2 * p],     ph, &vl4[0]);
                mma_bf16(o_acc[2 * p + 1], ph, &vl4[2]);
            }
        }
    }

    const float inv0 = 1.f / l0, inv1 = 1.f / l1;
#pragma unroll
    for (int nf = 0; nf < 8; nf++) {
        int col = nf * 8 + (lane & 3) * 2;
        store_split2(Ohi, Olo, qk_base + (size_t)r0 * DMODEL + col,
                     o_acc[nf][0] * inv0, o_acc[nf][1] * inv0);
        store_split2(Ohi, Olo, qk_base + (size_t)(r0 + 8) * DMODEL + col,
                     o_acc[nf][2] * inv1, o_acc[nf][3] * inv1);
    }
}

// ---------------------------------------------------------------------------
// Launch
// ---------------------------------------------------------------------------
extern "C" void kernel_launch(void* const* d_in, const int* in_sizes, int n_in,
                              void* d_out, int out_size)
{
    const float* x  = (const float*)d_in[0];
    const float* Wq = (const float*)d_in[1];
    const float* Wk = (const float*)d_in[2];
    const float* Wv = (const float*)d_in[3];
    const float* Wo = (const float*)d_in[4];
    const int*   tp = (const int*)d_in[5];
    float* out = (float*)d_out;

    __nv_bfloat16 *ahi, *alo, *whi, *wlo, *qhi, *qlo, *khi, *klo, *vthi, *vtlo;
    float2* cs;
    cudaGetSymbolAddress((void**)&ahi,  g_ahi);
    cudaGetSymbolAddress((void**)&alo,  g_alo);
    cudaGetSymbolAddress((void**)&whi,  g_whi);
    cudaGetSymbolAddress((void**)&wlo,  g_wlo);
    cudaGetSymbolAddress((void**)&qhi,  g_qhi);
    cudaGetSymbolAddress((void**)&qlo,  g_qlo);
    cudaGetSymbolAddress((void**)&khi,  g_khi);
    cudaGetSymbolAddress((void**)&klo,  g_klo);
    cudaGetSymbolAddress((void**)&vthi, g_vthi);
    cudaGetSymbolAddress((void**)&vtlo, g_vtlo);
    cudaGetSymbolAddress((void**)&cs,   g_cs);

    cudaFuncSetAttribute(gemm_qkv, cudaFuncAttributeMaxDynamicSharedMemorySize, GEMM_SMEM);
    cudaFuncSetAttribute(gemm_out, cudaFuncAttributeMaxDynamicSharedMemorySize, GEMM_SMEM);
    cudaFuncSetAttribute(attn_mma, cudaFuncAttributeMaxDynamicSharedMemorySize, AT_SMEM);

    const int nsplit = MTOT * DMODEL / 4 + WSZ;

    split_all<<<(nsplit + 255) / 256, 256>>>(x, Wq, Wk, Wv, Wo, ahi, alo, whi, wlo);
    rope_table<<<(SEQ * 32 + 255) / 256, 256>>>(cs, tp);

    gemm_qkv<<<dim3(DMODEL / 128, MTOT / 128, 3), 256, GEMM_SMEM>>>(
        ahi, alo, whi, wlo, qhi, qlo, khi, klo, vthi, vtlo, cs);

    attn_mma<<<dim3(SEQ / 128, NHEADS, BATCH), 256, AT_SMEM>>>(
        qhi, qlo, khi, klo, vthi, vtlo, ahi, alo);

    gemm_out<<<dim3(DMODEL / 128, MTOT / 128), 256, GEMM_SMEM>>>(
        ahi, alo, whi + (size_t)3 * WSZ, wlo + (size_t)3 * WSZ, out);
}